// round 2
// baseline (speedup 1.0000x reference)
#include <cuda_runtime.h>
#include <cuda_fp16.h>
#include <cstdint>

#define N_NODES 8192
#define INC 512
#define OUTC 256
#define ALPHA 0.5f

// ---------------- scratch (device globals; no allocations allowed) ----------------
__device__ float  g_Wh  [N_NODES * OUTC];            // 8 MB   fp32 Wh
__device__ __half g_WhT [OUTC * N_NODES];            // 4 MB   fp16 Wh^T (B operand, K-major: [n][k])
__device__ float  g_Wh1 [N_NODES];
__device__ float  g_Wh2 [N_NODES];
__device__ float  g_gmax2;
__device__ float  g_srow[N_NODES];                   // softmax denominators
__device__ __half g_P   [(size_t)N_NODES * N_NODES]; // 128 MB unnormalized attention (fp16)

// ================= K1: Wh = h @ W   (fp32 SIMT, M=8192 N=256 K=512) =================
__global__ void __launch_bounds__(256) k1_gemm(const float* __restrict__ h, const float* __restrict__ W) {
    __shared__ float As[16][64];
    __shared__ float Bs[16][64];
    int tid = threadIdx.x;
    int tx = tid & 15, ty = tid >> 4;
    int bm0 = blockIdx.y * 64, bn0 = blockIdx.x * 64;
    float acc[4][4] = {};
    for (int k0 = 0; k0 < INC; k0 += 16) {
        {   // load h tile [64 x 16]
            int r = tid >> 2, kq = (tid & 3) * 4;
            float4 v = *reinterpret_cast<const float4*>(h + (size_t)(bm0 + r) * INC + k0 + kq);
            As[kq + 0][r] = v.x; As[kq + 1][r] = v.y; As[kq + 2][r] = v.z; As[kq + 3][r] = v.w;
        }
        {   // load W tile [16 x 64]
            int kk = tid >> 4, nq = (tid & 15) * 4;
            float4 v = *reinterpret_cast<const float4*>(W + (size_t)(k0 + kk) * OUTC + bn0 + nq);
            *reinterpret_cast<float4*>(&Bs[kk][nq]) = v;
        }
        __syncthreads();
        #pragma unroll
        for (int kk = 0; kk < 16; kk++) {
            float4 av = *reinterpret_cast<const float4*>(&As[kk][ty * 4]);
            float4 bv = *reinterpret_cast<const float4*>(&Bs[kk][tx * 4]);
            float aa[4] = {av.x, av.y, av.z, av.w};
            float bb[4] = {bv.x, bv.y, bv.z, bv.w};
            #pragma unroll
            for (int i = 0; i < 4; i++)
                #pragma unroll
                for (int j = 0; j < 4; j++)
                    acc[i][j] += aa[i] * bb[j];
        }
        __syncthreads();
    }
    #pragma unroll
    for (int i = 0; i < 4; i++) {
        float4 v = {acc[i][0], acc[i][1], acc[i][2], acc[i][3]};
        *reinterpret_cast<float4*>(g_Wh + (size_t)(bm0 + ty * 4 + i) * OUTC + bn0 + tx * 4) = v;
    }
}

// ================= K2: Wh1/Wh2 GEMVs (warp per row) =================
__global__ void __launch_bounds__(256) k2_attvec(const float* __restrict__ a) {
    int tid = threadIdx.x, lid = tid & 31, wrp = tid >> 5;
    int r = blockIdx.x * 8 + wrp;
    const float* row = g_Wh + (size_t)r * OUTC;
    float s1 = 0.f, s2 = 0.f;
    #pragma unroll
    for (int t = 0; t < 8; t++) {
        int n = lid + t * 32;
        float w = row[n];
        s1 += w * a[n];
        s2 += w * a[OUTC + n];
    }
    #pragma unroll
    for (int o = 16; o > 0; o >>= 1) {
        s1 += __shfl_xor_sync(0xFFFFFFFF, s1, o);
        s2 += __shfl_xor_sync(0xFFFFFFFF, s2, o);
    }
    if (lid == 0) { g_Wh1[r] = s1; g_Wh2[r] = s2; }
}

// ================= K2b: global max of Wh2 =================
__global__ void __launch_bounds__(256) k2b_max() {
    __shared__ float red[256];
    int tid = threadIdx.x;
    float m = -1e30f;
    for (int j = tid; j < N_NODES; j += 256) m = fmaxf(m, g_Wh2[j]);
    red[tid] = m; __syncthreads();
    for (int o = 128; o > 0; o >>= 1) { if (tid < o) red[tid] = fmaxf(red[tid], red[tid + o]); __syncthreads(); }
    if (tid == 0) g_gmax2 = red[0];
}

// ================= K2c: WhT fp16 transpose =================
__global__ void k2c_transpose() {
    __shared__ float tile[32][33];
    int tx = threadIdx.x, ty = threadIdx.y;
    int i0 = blockIdx.x * 32, n0 = blockIdx.y * 32;
    #pragma unroll
    for (int k = 0; k < 32; k += 8)
        tile[ty + k][tx] = g_Wh[(size_t)(i0 + ty + k) * OUTC + n0 + tx];
    __syncthreads();
    #pragma unroll
    for (int k = 0; k < 32; k += 8)
        g_WhT[(size_t)(n0 + ty + k) * N_NODES + i0 + tx] = __float2half(tile[tx][ty + k]);
}

// ================= K3: single-pass masked exp + row sum (P fp16) =================
// p_ij = adj ? exp(lrelu(Wh1_i + Wh2_j) - B_i) : 0,   B_i = lrelu(Wh1_i + max_j Wh2_j) >= row max
// Row-shift cancels in softmax normalization; p <= 1 so fp16-safe.
__global__ void __launch_bounds__(256) k3_softmax(const int* __restrict__ adj) {
    __shared__ float red[256];
    int i = blockIdx.x, tid = threadIdx.x;
    float wh1 = g_Wh1[i];
    float xB = wh1 + g_gmax2;
    float B = xB > 0.f ? xB : ALPHA * xB;
    const int4* arow = reinterpret_cast<const int4*>(adj + (size_t)i * N_NODES);
    const float4* w2p = reinterpret_cast<const float4*>(g_Wh2);
    float s = 0.f;
    #pragma unroll 2
    for (int j4 = tid; j4 < N_NODES / 4; j4 += 256) {
        int4 av = arow[j4];
        float4 w2 = w2p[j4];
        float x0 = wh1 + w2.x, x1 = wh1 + w2.y, x2 = wh1 + w2.z, x3 = wh1 + w2.w;
        float e0 = x0 > 0.f ? x0 : ALPHA * x0;
        float e1 = x1 > 0.f ? x1 : ALPHA * x1;
        float e2 = x2 > 0.f ? x2 : ALPHA * x2;
        float e3 = x3 > 0.f ? x3 : ALPHA * x3;
        float p0 = av.x > 0 ? __expf(e0 - B) : 0.f;
        float p1 = av.y > 0 ? __expf(e1 - B) : 0.f;
        float p2 = av.z > 0 ? __expf(e2 - B) : 0.f;
        float p3 = av.w > 0 ? __expf(e3 - B) : 0.f;
        __half h0 = __float2half(p0), h1 = __float2half(p1);
        __half h2 = __float2half(p2), h3 = __float2half(p3);
        // sum the fp16-rounded values so numerator/denominator match exactly
        s += __half2float(h0) + __half2float(h1) + __half2float(h2) + __half2float(h3);
        __half2 v0 = __halves2half2(h0, h1), v1 = __halves2half2(h2, h3);
        uint2 pk;
        pk.x = *reinterpret_cast<uint32_t*>(&v0);
        pk.y = *reinterpret_cast<uint32_t*>(&v1);
        *reinterpret_cast<uint2*>(g_P + (size_t)i * N_NODES + (size_t)j4 * 4) = pk;
    }
    red[tid] = s; __syncthreads();
    for (int o = 128; o > 0; o >>= 1) { if (tid < o) red[tid] += red[tid + o]; __syncthreads(); }
    if (tid == 0) g_srow[i] = red[0];
}

// ================= K4: out = relu( (P @ Wh) / s ) via mma.sync HMMA =================
// BM=64, BN=256, BK=32. 256 threads = 8 warps (2 m x 4 n), warp tile 32x64.
// A = P [8192 x 8192] fp16 row-major; B = g_WhT [256(n) x 8192(k)] fp16 (col-major for mma).
// SMEM rows padded to 40 halves (80B) -> conflict-free ldmatrix.

#define K4_BM 64
#define K4_BN 256
#define K4_BK 32
#define K4_NK (N_NODES / K4_BK)
#define K4_ROWH 40                              // padded row length in halves
#define K4_ROWB 80                              // row bytes
#define K4_A_BYTES (K4_BM * K4_ROWB)            // 5120
#define K4_B_BYTES (K4_BN * K4_ROWB)            // 20480
#define K4_SMEM_TOT (2 * K4_A_BYTES + 2 * K4_B_BYTES)  // 51200

__device__ __forceinline__ uint32_t smem_u32(const void* p) {
    uint32_t a;
    asm("{ .reg .u64 t; cvta.to.shared.u64 t, %1; cvt.u32.u64 %0, t; }" : "=r"(a) : "l"(p));
    return a;
}
__device__ __forceinline__ void cp16(uint32_t s, const void* g) {
    asm volatile("cp.async.cg.shared.global [%0], [%1], 16;" :: "r"(s), "l"(g) : "memory");
}
__device__ __forceinline__ void cp_commit() { asm volatile("cp.async.commit_group;" ::: "memory"); }
__device__ __forceinline__ void cp_wait0()  { asm volatile("cp.async.wait_group 0;" ::: "memory"); }

__device__ __forceinline__ void ldsm4(uint32_t* r, uint32_t addr) {
    asm volatile("ldmatrix.sync.aligned.m8n8.x4.shared.b16 {%0,%1,%2,%3}, [%4];"
                 : "=r"(r[0]), "=r"(r[1]), "=r"(r[2]), "=r"(r[3]) : "r"(addr));
}
__device__ __forceinline__ void hmma16816(float* c, const uint32_t* a, const uint32_t* b) {
    asm volatile("mma.sync.aligned.m16n8k16.row.col.f32.f16.f16.f32 "
                 "{%0,%1,%2,%3}, {%4,%5,%6,%7}, {%8,%9}, {%0,%1,%2,%3};"
                 : "+f"(c[0]), "+f"(c[1]), "+f"(c[2]), "+f"(c[3])
                 : "r"(a[0]), "r"(a[1]), "r"(a[2]), "r"(a[3]), "r"(b[0]), "r"(b[1]));
}

__device__ __forceinline__ void k4_load(uint32_t sbase, int buf, int rowBase, int k0, int t) {
    int r = t >> 2, cb = (t & 3) * 8;        // 8 halves = 16B per cp.async
    // A tile: 64 rows x 32 k
    uint32_t sA = sbase + buf * K4_A_BYTES + r * K4_ROWB + (cb * 2) * 0 + (t & 3) * 16;
    cp16(sbase + buf * K4_A_BYTES + r * K4_ROWB + (t & 3) * 16,
         g_P + (size_t)(rowBase + r) * N_NODES + k0 + cb);
    (void)sA;
    // B tile: 256 rows x 32 k
    #pragma unroll
    for (int q = 0; q < 4; q++) {
        int n = (t >> 2) + 64 * q;
        cp16(sbase + 2 * K4_A_BYTES + buf * K4_B_BYTES + n * K4_ROWB + (t & 3) * 16,
             g_WhT + (size_t)n * N_NODES + k0 + cb);
    }
}

__global__ void __launch_bounds__(256, 1) k4_gemm(float* __restrict__ out) {
    extern __shared__ char smem[];
    uint32_t sbase = smem_u32(smem);
    int t = threadIdx.x, wid = t >> 5, l = t & 31;
    int rowBase = blockIdx.x * K4_BM;
    int wm = wid >> 2, wn = wid & 3;          // warp grid 2 x 4
    int m0 = wm * 32, n0 = wn * 64;

    float acc[2][8][4];
    #pragma unroll
    for (int mi = 0; mi < 2; mi++)
        #pragma unroll
        for (int ni = 0; ni < 8; ni++)
            #pragma unroll
            for (int c = 0; c < 4; c++) acc[mi][ni][c] = 0.f;

    // precompute ldmatrix lane address components
    int sub = l >> 3, lr = l & 7;
    int aRowOff = (sub & 1) * 8 + lr;         // within m16 frag
    int aByte   = (sub >> 1) * 16;
    int bRowOff = ((sub >> 1) & 1) * 8 + lr;  // within n16 pair
    int bByte   = (sub & 1) * 16;

    k4_load(sbase, 0, rowBase, 0, t);
    cp_commit();

    for (int kc = 0; kc < K4_NK; kc++) {
        int buf = kc & 1;
        cp_wait0();
        __syncthreads();
        if (kc + 1 < K4_NK) { k4_load(sbase, buf ^ 1, rowBase, (kc + 1) * K4_BK, t); cp_commit(); }

        uint32_t aT = sbase + buf * K4_A_BYTES;
        uint32_t bT = sbase + 2 * K4_A_BYTES + buf * K4_B_BYTES;
        #pragma unroll
        for (int ks = 0; ks < 2; ks++) {      // two k16 steps
            int ksb = ks * 32;                // 16 halves = 32 bytes
            uint32_t afr[2][4], bfr[4][4];
            #pragma unroll
            for (int mi = 0; mi < 2; mi++)
                ldsm4(afr[mi], aT + (m0 + mi * 16 + aRowOff) * K4_ROWB + ksb + aByte);
            #pragma unroll
            for (int pi = 0; pi < 4; pi++)
                ldsm4(bfr[pi], bT + (n0 + pi * 16 + bRowOff) * K4_ROWB + ksb + bByte);
            #pragma unroll
            for (int mi = 0; mi < 2; mi++)
                #pragma unroll
                for (int ni = 0; ni < 8; ni++)
                    hmma16816(acc[mi][ni], afr[mi], &bfr[ni >> 1][(ni & 1) * 2]);
        }
        __syncthreads();
    }

    // epilogue: divide by row sum, relu, store
    int rl = rowBase + m0 + (l >> 2);
    float inv[4];
    #pragma unroll
    for (int mi = 0; mi < 2; mi++)
        #pragma unroll
        for (int hh = 0; hh < 2; hh++)
            inv[mi * 2 + hh] = 1.0f / g_srow[rl + mi * 16 + hh * 8];
    #pragma unroll
    for (int mi = 0; mi < 2; mi++)
        #pragma unroll
        for (int hh = 0; hh < 2; hh++) {
            int row = rl + mi * 16 + hh * 8;
            float iv = inv[mi * 2 + hh];
            #pragma unroll
            for (int ni = 0; ni < 8; ni++) {
                int col = n0 + ni * 8 + (l & 3) * 2;
                float2 v;
                v.x = fmaxf(acc[mi][ni][hh * 2 + 0] * iv, 0.f);
                v.y = fmaxf(acc[mi][ni][hh * 2 + 1] * iv, 0.f);
                *reinterpret_cast<float2*>(out + (size_t)row * OUTC + col) = v;
            }
        }
}

// ================= launch =================
extern "C" void kernel_launch(void* const* d_in, const int* in_sizes, int n_in,
                              void* d_out, int out_size) {
    const float* h   = (const float*)d_in[0];
    const int*   adj = (const int*)d_in[1];
    const float* W   = (const float*)d_in[2];
    const float* a   = (const float*)d_in[3];
    float* out = (float*)d_out;

    k1_gemm<<<dim3(OUTC / 64, N_NODES / 64), 256>>>(h, W);
    k2_attvec<<<N_NODES / 8, 256>>>(a);
    k2b_max<<<1, 256>>>();
    k2c_transpose<<<dim3(N_NODES / 32, OUTC / 32), dim3(32, 8)>>>();
    k3_softmax<<<N_NODES, 256>>>(adj);

    static bool attr_set = false;
    if (!attr_set) {
        cudaFuncSetAttribute(k4_gemm, cudaFuncAttributeMaxDynamicSharedMemorySize, K4_SMEM_TOT);
        attr_set = true;
    }
    k4_gemm<<<N_NODES / K4_BM, 256, K4_SMEM_TOT>>>(out);
}

// round 3
// speedup vs baseline: 1.3029x; 1.3029x over previous
#include <cuda_runtime.h>
#include <cuda_fp16.h>
#include <cstdint>

#define N_NODES 8192
#define INC 512
#define OUTC 256
#define ALPHA 0.5f

// ---------------- scratch (device globals; no allocations allowed) ----------------
__device__ float  g_Wh  [N_NODES * OUTC];            // 8 MB   fp32 Wh
__device__ __half g_WhT [OUTC * N_NODES];            // 4 MB   fp16 Wh^T (B operand, K-major: [n][k])
__device__ float  g_Wh1 [N_NODES];
__device__ float  g_Wh2 [N_NODES];
__device__ float  g_gmax2;
__device__ float  g_srow[N_NODES];                   // softmax denominators
__device__ __half g_P   [(size_t)N_NODES * N_NODES]; // 128 MB unnormalized attention (fp16)

// ================= K1: Wh = h @ W   (fp32 SIMT, M=8192 N=256 K=512) =================
// BM=128, BN=64, BK=16; 256 threads; 8x4 register tile (64 FMA : 3 LDS.128 -> FMA-bound).
__global__ void __launch_bounds__(256) k1_gemm(const float* __restrict__ h, const float* __restrict__ W) {
    __shared__ float As[16][128];   // [k][m]
    __shared__ float Bs[16][64];    // [k][n]
    int tid = threadIdx.x;
    int tx = tid & 15, ty = tid >> 4;        // tx: 4 cols, ty: 8 rows
    int bm0 = blockIdx.y * 128, bn0 = blockIdx.x * 64;

    float acc[8][4] = {};
    float4 pa[2], pb;

    // prologue loads (tile k0=0)
    {
        int idx0 = tid, idx1 = tid + 256;
        int r0 = idx0 >> 2, q0 = idx0 & 3;
        int r1 = idx1 >> 2, q1 = idx1 & 3;
        pa[0] = *reinterpret_cast<const float4*>(h + (size_t)(bm0 + r0) * INC + q0 * 4);
        pa[1] = *reinterpret_cast<const float4*>(h + (size_t)(bm0 + r1) * INC + q1 * 4);
        int kk = tid >> 4, nq = tid & 15;
        pb = *reinterpret_cast<const float4*>(W + (size_t)kk * OUTC + bn0 + nq * 4);
    }

    for (int k0 = 0; k0 < INC; k0 += 16) {
        // store prefetched tile to smem
        {
            int idx0 = tid, idx1 = tid + 256;
            int r0 = idx0 >> 2, q0 = idx0 & 3;
            int r1 = idx1 >> 2, q1 = idx1 & 3;
            As[q0 * 4 + 0][r0] = pa[0].x; As[q0 * 4 + 1][r0] = pa[0].y;
            As[q0 * 4 + 2][r0] = pa[0].z; As[q0 * 4 + 3][r0] = pa[0].w;
            As[q1 * 4 + 0][r1] = pa[1].x; As[q1 * 4 + 1][r1] = pa[1].y;
            As[q1 * 4 + 2][r1] = pa[1].z; As[q1 * 4 + 3][r1] = pa[1].w;
            int kk = tid >> 4, nq = tid & 15;
            *reinterpret_cast<float4*>(&Bs[kk][nq * 4]) = pb;
        }
        __syncthreads();
        // prefetch next tile
        if (k0 + 16 < INC) {
            int kn = k0 + 16;
            int idx0 = tid, idx1 = tid + 256;
            int r0 = idx0 >> 2, q0 = idx0 & 3;
            int r1 = idx1 >> 2, q1 = idx1 & 3;
            pa[0] = *reinterpret_cast<const float4*>(h + (size_t)(bm0 + r0) * INC + kn + q0 * 4);
            pa[1] = *reinterpret_cast<const float4*>(h + (size_t)(bm0 + r1) * INC + kn + q1 * 4);
            int kk = tid >> 4, nq = tid & 15;
            pb = *reinterpret_cast<const float4*>(W + (size_t)(kn + kk) * OUTC + bn0 + nq * 4);
        }
        // compute
        #pragma unroll
        for (int kk = 0; kk < 16; kk++) {
            float4 a0 = *reinterpret_cast<const float4*>(&As[kk][ty * 8]);
            float4 a1 = *reinterpret_cast<const float4*>(&As[kk][ty * 8 + 4]);
            float4 bv = *reinterpret_cast<const float4*>(&Bs[kk][tx * 4]);
            float aa[8] = {a0.x, a0.y, a0.z, a0.w, a1.x, a1.y, a1.z, a1.w};
            float bb[4] = {bv.x, bv.y, bv.z, bv.w};
            #pragma unroll
            for (int i = 0; i < 8; i++)
                #pragma unroll
                for (int j = 0; j < 4; j++)
                    acc[i][j] += aa[i] * bb[j];
        }
        __syncthreads();
    }
    #pragma unroll
    for (int i = 0; i < 8; i++) {
        float4 v = {acc[i][0], acc[i][1], acc[i][2], acc[i][3]};
        *reinterpret_cast<float4*>(g_Wh + (size_t)(bm0 + ty * 8 + i) * OUTC + bn0 + tx * 4) = v;
    }
}

// ================= K2: Wh1/Wh2 GEMVs (warp per row) =================
__global__ void __launch_bounds__(256) k2_attvec(const float* __restrict__ a) {
    int tid = threadIdx.x, lid = tid & 31, wrp = tid >> 5;
    int r = blockIdx.x * 8 + wrp;
    const float* row = g_Wh + (size_t)r * OUTC;
    float s1 = 0.f, s2 = 0.f;
    #pragma unroll
    for (int t = 0; t < 8; t++) {
        int n = lid + t * 32;
        float w = row[n];
        s1 += w * a[n];
        s2 += w * a[OUTC + n];
    }
    #pragma unroll
    for (int o = 16; o > 0; o >>= 1) {
        s1 += __shfl_xor_sync(0xFFFFFFFF, s1, o);
        s2 += __shfl_xor_sync(0xFFFFFFFF, s2, o);
    }
    if (lid == 0) { g_Wh1[r] = s1; g_Wh2[r] = s2; }
}

// ================= K2b: global max of Wh2 =================
__global__ void __launch_bounds__(256) k2b_max() {
    __shared__ float red[256];
    int tid = threadIdx.x;
    float m = -1e30f;
    for (int j = tid; j < N_NODES; j += 256) m = fmaxf(m, g_Wh2[j]);
    red[tid] = m; __syncthreads();
    for (int o = 128; o > 0; o >>= 1) { if (tid < o) red[tid] = fmaxf(red[tid], red[tid + o]); __syncthreads(); }
    if (tid == 0) g_gmax2 = red[0];
}

// ================= K2c: WhT fp16 transpose =================
__global__ void k2c_transpose() {
    __shared__ float tile[32][33];
    int tx = threadIdx.x, ty = threadIdx.y;
    int i0 = blockIdx.x * 32, n0 = blockIdx.y * 32;
    #pragma unroll
    for (int k = 0; k < 32; k += 8)
        tile[ty + k][tx] = g_Wh[(size_t)(i0 + ty + k) * OUTC + n0 + tx];
    __syncthreads();
    #pragma unroll
    for (int k = 0; k < 32; k += 8)
        g_WhT[(size_t)(n0 + ty + k) * N_NODES + i0 + tx] = __float2half(tile[tx][ty + k]);
}

// ================= K3: single-pass masked exp + row sum (P fp16) =================
__global__ void __launch_bounds__(256) k3_softmax(const int* __restrict__ adj) {
    __shared__ float red[256];
    int i = blockIdx.x, tid = threadIdx.x;
    float wh1 = g_Wh1[i];
    float xB = wh1 + g_gmax2;
    float B = xB > 0.f ? xB : ALPHA * xB;
    const int4* arow = reinterpret_cast<const int4*>(adj + (size_t)i * N_NODES);
    const float4* w2p = reinterpret_cast<const float4*>(g_Wh2);
    float s = 0.f;
    #pragma unroll 4
    for (int j4 = tid; j4 < N_NODES / 4; j4 += 256) {
        int4 av = __ldcs(&arow[j4]);         // evict-first: adj never reused
        float4 w2 = w2p[j4];                  // 32KB, L1/L2 resident
        float x0 = wh1 + w2.x, x1 = wh1 + w2.y, x2 = wh1 + w2.z, x3 = wh1 + w2.w;
        float e0 = x0 > 0.f ? x0 : ALPHA * x0;
        float e1 = x1 > 0.f ? x1 : ALPHA * x1;
        float e2 = x2 > 0.f ? x2 : ALPHA * x2;
        float e3 = x3 > 0.f ? x3 : ALPHA * x3;
        float p0 = av.x > 0 ? __expf(e0 - B) : 0.f;
        float p1 = av.y > 0 ? __expf(e1 - B) : 0.f;
        float p2 = av.z > 0 ? __expf(e2 - B) : 0.f;
        float p3 = av.w > 0 ? __expf(e3 - B) : 0.f;
        __half h0 = __float2half(p0), h1 = __float2half(p1);
        __half h2 = __float2half(p2), h3 = __float2half(p3);
        s += __half2float(h0) + __half2float(h1) + __half2float(h2) + __half2float(h3);
        __half2 v0 = __halves2half2(h0, h1), v1 = __halves2half2(h2, h3);
        uint2 pk;
        pk.x = *reinterpret_cast<uint32_t*>(&v0);
        pk.y = *reinterpret_cast<uint32_t*>(&v1);
        __stcs(reinterpret_cast<uint2*>(g_P + (size_t)i * N_NODES + (size_t)j4 * 4), pk);
    }
    red[tid] = s; __syncthreads();
    for (int o = 128; o > 0; o >>= 1) { if (tid < o) red[tid] += red[tid + o]; __syncthreads(); }
    if (tid == 0) g_srow[i] = red[0];
}

// ================= K4: out = relu( (P @ Wh) / s ) via mma.sync HMMA =================
// BM=64, BN=256, BK=32, 3-stage cp.async pipeline, one __syncthreads per K-iter.
// 8 warps (2m x 4n), warp tile 32x64. SMEM rows padded to 80B -> conflict-free ldmatrix.

#define K4_BM 64
#define K4_BN 256
#define K4_BK 32
#define K4_NK (N_NODES / K4_BK)
#define K4_ROWB 80                               // padded row bytes (40 halves)
#define K4_A_BYTES (K4_BM * K4_ROWB)             // 5120
#define K4_B_BYTES (K4_BN * K4_ROWB)             // 20480
#define K4_STAGE_BYTES (K4_A_BYTES + K4_B_BYTES) // 25600
#define K4_STAGES 3
#define K4_SMEM_TOT (K4_STAGES * K4_STAGE_BYTES) // 76800

__device__ __forceinline__ uint32_t smem_u32(const void* p) {
    uint32_t a;
    asm("{ .reg .u64 t; cvta.to.shared.u64 t, %1; cvt.u32.u64 %0, t; }" : "=r"(a) : "l"(p));
    return a;
}
__device__ __forceinline__ void cp16(uint32_t s, const void* g) {
    asm volatile("cp.async.cg.shared.global [%0], [%1], 16;" :: "r"(s), "l"(g) : "memory");
}
__device__ __forceinline__ void cp_commit() { asm volatile("cp.async.commit_group;" ::: "memory"); }
__device__ __forceinline__ void cp_wait1()  { asm volatile("cp.async.wait_group 1;" ::: "memory"); }
__device__ __forceinline__ void cp_wait0()  { asm volatile("cp.async.wait_group 0;" ::: "memory"); }

__device__ __forceinline__ void ldsm4(uint32_t* r, uint32_t addr) {
    asm volatile("ldmatrix.sync.aligned.m8n8.x4.shared.b16 {%0,%1,%2,%3}, [%4];"
                 : "=r"(r[0]), "=r"(r[1]), "=r"(r[2]), "=r"(r[3]) : "r"(addr));
}
__device__ __forceinline__ void hmma16816(float* c, const uint32_t* a, const uint32_t* b) {
    asm volatile("mma.sync.aligned.m16n8k16.row.col.f32.f16.f16.f32 "
                 "{%0,%1,%2,%3}, {%4,%5,%6,%7}, {%8,%9}, {%0,%1,%2,%3};"
                 : "+f"(c[0]), "+f"(c[1]), "+f"(c[2]), "+f"(c[3])
                 : "r"(a[0]), "r"(a[1]), "r"(a[2]), "r"(a[3]), "r"(b[0]), "r"(b[1]));
}

__device__ __forceinline__ void k4_load(uint32_t stageBase, int rowBase, int k0, int t) {
    int r = t >> 2, cb = (t & 3) * 8;        // 8 halves = 16B per cp.async
    // A tile: 64 rows x 32 k
    cp16(stageBase + r * K4_ROWB + (t & 3) * 16,
         g_P + (size_t)(rowBase + r) * N_NODES + k0 + cb);
    // B tile: 256 rows x 32 k
    #pragma unroll
    for (int q = 0; q < 4; q++) {
        int n = r + 64 * q;
        cp16(stageBase + K4_A_BYTES + n * K4_ROWB + (t & 3) * 16,
             g_WhT + (size_t)n * N_NODES + k0 + cb);
    }
}

__global__ void __launch_bounds__(256, 1) k4_gemm(float* __restrict__ out) {
    extern __shared__ char smem[];
    uint32_t sbase = smem_u32(smem);
    int t = threadIdx.x, wid = t >> 5, l = t & 31;
    int rowBase = blockIdx.x * K4_BM;
    int wm = wid >> 2, wn = wid & 3;          // warp grid 2 x 4
    int m0 = wm * 32, n0 = wn * 64;

    float acc[2][8][4];
    #pragma unroll
    for (int mi = 0; mi < 2; mi++)
        #pragma unroll
        for (int ni = 0; ni < 8; ni++)
            #pragma unroll
            for (int c = 0; c < 4; c++) acc[mi][ni][c] = 0.f;

    // ldmatrix lane address components
    int sub = l >> 3, lr = l & 7;
    int aRowOff = (sub & 1) * 8 + lr;
    int aByte   = (sub >> 1) * 16;
    int bRowOff = ((sub >> 1) & 1) * 8 + lr;
    int bByte   = (sub & 1) * 16;

    // prologue: stages 0 and 1 in flight
    k4_load(sbase, rowBase, 0, t);            cp_commit();
    k4_load(sbase + K4_STAGE_BYTES, rowBase, K4_BK, t); cp_commit();

    int cs = 0;                                // compute stage
    int ls = 2;                                // next load stage
    for (int kc = 0; kc < K4_NK; kc++) {
        cp_wait1();                            // stage kc resident
        __syncthreads();                       // everyone done computing kc-1 (buf ls)
        if (kc + 2 < K4_NK) {
            k4_load(sbase + ls * K4_STAGE_BYTES, rowBase, (kc + 2) * K4_BK, t);
            cp_commit();
        } else if (kc + 2 == K4_NK + 1) {
            cp_wait0();                        // drain tail so wait1 semantics hold (no-op safety)
        }

        uint32_t aT = sbase + cs * K4_STAGE_BYTES;
        uint32_t bT = aT + K4_A_BYTES;
        #pragma unroll
        for (int ks = 0; ks < 2; ks++) {       // two k16 steps
            int ksb = ks * 32;                 // 16 halves = 32 bytes
            uint32_t afr[2][4], bfr[4][4];
            #pragma unroll
            for (int mi = 0; mi < 2; mi++)
                ldsm4(afr[mi], aT + (m0 + mi * 16 + aRowOff) * K4_ROWB + ksb + aByte);
            #pragma unroll
            for (int pi = 0; pi < 4; pi++)
                ldsm4(bfr[pi], bT + (n0 + pi * 16 + bRowOff) * K4_ROWB + ksb + bByte);
            #pragma unroll
            for (int mi = 0; mi < 2; mi++)
                #pragma unroll
                for (int ni = 0; ni < 8; ni++)
                    hmma16816(acc[mi][ni], afr[mi], &bfr[ni >> 1][(ni & 1) * 2]);
        }
        cs = (cs == 2) ? 0 : cs + 1;
        ls = (ls == 2) ? 0 : ls + 1;
    }

    // epilogue: divide by row sum, relu, store
    int rl = rowBase + m0 + (l >> 2);
    #pragma unroll
    for (int mi = 0; mi < 2; mi++)
        #pragma unroll
        for (int hh = 0; hh < 2; hh++) {
            int row = rl + mi * 16 + hh * 8;
            float iv = 1.0f / g_srow[row];
            #pragma unroll
            for (int ni = 0; ni < 8; ni++) {
                int col = n0 + ni * 8 + (l & 3) * 2;
                float2 v;
                v.x = fmaxf(acc[mi][ni][hh * 2 + 0] * iv, 0.f);
                v.y = fmaxf(acc[mi][ni][hh * 2 + 1] * iv, 0.f);
                *reinterpret_cast<float2*>(out + (size_t)row * OUTC + col) = v;
            }
        }
}

// ================= launch =================
extern "C" void kernel_launch(void* const* d_in, const int* in_sizes, int n_in,
                              void* d_out, int out_size) {
    const float* h   = (const float*)d_in[0];
    const int*   adj = (const int*)d_in[1];
    const float* W   = (const float*)d_in[2];
    const float* a   = (const float*)d_in[3];
    float* out = (float*)d_out;

    k1_gemm<<<dim3(OUTC / 64, N_NODES / 128), 256>>>(h, W);
    k2_attvec<<<N_NODES / 8, 256>>>(a);
    k2b_max<<<1, 256>>>();
    k2c_transpose<<<dim3(N_NODES / 32, OUTC / 32), dim3(32, 8)>>>();
    k3_softmax<<<N_NODES, 256>>>(adj);

    static bool attr_set = false;
    if (!attr_set) {
        cudaFuncSetAttribute(k4_gemm, cudaFuncAttributeMaxDynamicSharedMemorySize, K4_SMEM_TOT);
        attr_set = true;
    }
    k4_gemm<<<N_NODES / K4_BM, 256, K4_SMEM_TOT>>>(out);
}